// round 1
// baseline (speedup 1.0000x reference)
#include <cuda_runtime.h>
#include <cstdint>

// Problem constants
#define B_ 4
#define S_ 2048
#define E_ 768
#define H_ 12
#define D_ 64
#define SCALE_ 0.125f   // 1/sqrt(64)

// Scratch for Q/K/V in [B, H, S, D] layout (no cudaMalloc allowed)
__device__ float g_q[(size_t)B_ * H_ * S_ * D_];
__device__ float g_k[(size_t)B_ * H_ * S_ * D_];
__device__ float g_v[(size_t)B_ * H_ * S_ * D_];

// ---------------------------------------------------------------------------
// helpers
// ---------------------------------------------------------------------------
__device__ __forceinline__ uint32_t f2t(float f) {
    uint32_t u;
    asm("cvt.rna.tf32.f32 %0, %1;" : "=r"(u) : "f"(f));
    return u;
}

__device__ __forceinline__ void mma8(float c[4],
                                     uint32_t a0, uint32_t a1, uint32_t a2, uint32_t a3,
                                     uint32_t b0, uint32_t b1) {
    asm volatile(
        "mma.sync.aligned.m16n8k8.row.col.f32.tf32.tf32.f32 "
        "{%0,%1,%2,%3}, {%4,%5,%6,%7}, {%8,%9}, {%0,%1,%2,%3};"
        : "+f"(c[0]), "+f"(c[1]), "+f"(c[2]), "+f"(c[3])
        : "r"(a0), "r"(a1), "r"(a2), "r"(a3), "r"(b0), "r"(b1));
}

// ---------------------------------------------------------------------------
// Kernel 1: fused QKV projection  C[8192, 2304] = X[8192,768] @ W[768,2304] + b
// Scatters result into g_q / g_k / g_v as [B,H,S,D].
// Block: 256 threads (8 warps, 4x2), tile 128x128, BK=16, TF32 mma.
// ---------------------------------------------------------------------------
#define GA_STRIDE 40    // As[m][k] padded stride (conflict-free LDS.64)
#define GB_STRIDE 140   // Bs[k][n] padded stride (conflict-free LDS.32)

__global__ __launch_bounds__(256, 2) void qkv_gemm(
    const float* __restrict__ X, const float* __restrict__ W,
    const float* __restrict__ bias)
{
    __shared__ uint32_t As[128 * GA_STRIDE];
    __shared__ uint32_t Bs[16 * GB_STRIDE];

    const int tid  = threadIdx.x;
    const int lane = tid & 31;
    const int wid  = tid >> 5;
    const int g    = lane >> 2;     // groupID 0..7
    const int tg   = lane & 3;      // thread-in-group 0..3
    const int wm   = wid & 3;       // warp row 0..3 (32 rows each)
    const int wn   = wid >> 2;      // warp col 0..1 (64 cols each)
    const int mbase = blockIdx.y * 128;
    const int nbase = blockIdx.x * 128;

    float acc[2][8][4];
#pragma unroll
    for (int mi = 0; mi < 2; mi++)
#pragma unroll
        for (int ni = 0; ni < 8; ni++)
#pragma unroll
            for (int c = 0; c < 4; c++) acc[mi][ni][c] = 0.f;

    for (int k0 = 0; k0 < E_; k0 += 16) {
        // A tile 128x16 (row-major)
#pragma unroll
        for (int i = 0; i < 2; i++) {
            int j = i * 256 + tid;
            int r = j >> 2, c4 = (j & 3) * 4;
            float4 v = *reinterpret_cast<const float4*>(
                X + (size_t)(mbase + r) * E_ + k0 + c4);
            uint32_t* p = &As[r * GA_STRIDE + c4];
            p[0] = f2t(v.x); p[1] = f2t(v.y); p[2] = f2t(v.z); p[3] = f2t(v.w);
        }
        // B tile 16x128 (natural [k][n])
#pragma unroll
        for (int i = 0; i < 2; i++) {
            int j = i * 256 + tid;
            int kr = j >> 5, c4 = (j & 31) * 4;
            float4 v = *reinterpret_cast<const float4*>(
                W + (size_t)(k0 + kr) * (3 * E_) + nbase + c4);
            uint32_t* p = &Bs[kr * GB_STRIDE + c4];
            p[0] = f2t(v.x); p[1] = f2t(v.y); p[2] = f2t(v.z); p[3] = f2t(v.w);
        }
        __syncthreads();

#pragma unroll
        for (int kk = 0; kk < 2; kk++) {
            // permuted k-slots: thread tg owns logical k = kk*8 + {2tg, 2tg+1}
            uint2 a[2][2];
#pragma unroll
            for (int mi = 0; mi < 2; mi++) {
                int row = wm * 32 + mi * 16 + g;
                a[mi][0] = *reinterpret_cast<const uint2*>(
                    &As[row * GA_STRIDE + kk * 8 + 2 * tg]);
                a[mi][1] = *reinterpret_cast<const uint2*>(
                    &As[(row + 8) * GA_STRIDE + kk * 8 + 2 * tg]);
            }
#pragma unroll
            for (int ni = 0; ni < 8; ni++) {
                int col = wn * 64 + ni * 8 + g;
                uint32_t b0 = Bs[(kk * 8 + 2 * tg) * GB_STRIDE + col];
                uint32_t b1 = Bs[(kk * 8 + 2 * tg + 1) * GB_STRIDE + col];
#pragma unroll
                for (int mi = 0; mi < 2; mi++)
                    mma8(acc[mi][ni],
                         a[mi][0].x, a[mi][1].x, a[mi][0].y, a[mi][1].y, b0, b1);
            }
        }
        __syncthreads();
    }

    // Epilogue: + bias, scatter into g_q/g_k/g_v as [B,H,S,D]
#pragma unroll
    for (int mi = 0; mi < 2; mi++) {
#pragma unroll
        for (int ni = 0; ni < 8; ni++) {
            int n = nbase + wn * 64 + ni * 8 + 2 * tg;   // even
            int which = n / E_;
            int n2 = n - which * E_;
            int h = n2 >> 6, d = n2 & 63;
            float b0 = __ldg(bias + n), b1 = __ldg(bias + n + 1);
            float* basep = (which == 0) ? g_q : ((which == 1) ? g_k : g_v);
#pragma unroll
            for (int half = 0; half < 2; half++) {
                int m = mbase + wm * 32 + mi * 16 + g + half * 8;
                int b = m >> 11;          // m / 2048
                int s = m & 2047;
                float2 val = make_float2(acc[mi][ni][half * 2 + 0] + b0,
                                         acc[mi][ni][half * 2 + 1] + b1);
                *reinterpret_cast<float2*>(
                    basep + ((((size_t)b * H_ + h) * S_ + s) * D_ + d)) = val;
            }
        }
    }
}

// ---------------------------------------------------------------------------
// Kernel 2: causal ReLU attention per (q-tile 128, head).
//   S = Q Kt^T * scale ; P = relu(mask(S)) ; Y += P Vt      (all TF32 mma)
// Only kt <= 2*qt+1 tiles are visited (causal skipping).
// ---------------------------------------------------------------------------
#define AT_STRIDE 72   // Qs/Ks/Ps stride (conflict-free LDS.64 frag loads)
#define V_STRIDE  68   // Vs stride (conflict-free LDS.32 frag loads)
#define ATTN_SMEM_WORDS (128 * AT_STRIDE + 64 * AT_STRIDE + 128 * AT_STRIDE + 64 * V_STRIDE)
#define ATTN_SMEM_BYTES (ATTN_SMEM_WORDS * 4)

__global__ __launch_bounds__(256, 2) void attn_kernel(float* __restrict__ out)
{
    extern __shared__ uint32_t sh[];
    uint32_t* Qs = sh;                          // [128][72]  Q tile (tf32)
    uint32_t* Ks = Qs + 128 * AT_STRIDE;        // [64][72]   K tile
    uint32_t* Ps = Ks + 64 * AT_STRIDE;         // [128][72]  P = relu(masked S)
    uint32_t* Vs = Ps + 128 * AT_STRIDE;        // [64][68]   V tile (natural [s][d])

    const int tid  = threadIdx.x;
    const int lane = tid & 31;
    const int wid  = tid >> 5;
    const int g    = lane >> 2;
    const int tg   = lane & 3;
    const int wm   = wid & 3;    // 4 warps over 128 q rows
    const int wn   = wid >> 2;   // 2 warps over 64 cols
    const int qt   = blockIdx.x;
    const int bh   = blockIdx.y;
    const int qbase = qt * 128;

    const float* Qg = g_q + (size_t)bh * S_ * D_ + (size_t)qbase * D_;
    const float* Kg = g_k + (size_t)bh * S_ * D_;
    const float* Vg = g_v + (size_t)bh * S_ * D_;

    // stage Q tile (128x64) as tf32
#pragma unroll
    for (int i = 0; i < 8; i++) {
        int j = i * 256 + tid;
        int r = j >> 4, c4 = (j & 15) * 4;
        float4 v = *reinterpret_cast<const float4*>(Qg + r * 64 + c4);
        uint32_t* p = &Qs[r * AT_STRIDE + c4];
        p[0] = f2t(v.x); p[1] = f2t(v.y); p[2] = f2t(v.z); p[3] = f2t(v.w);
    }

    float yacc[2][4][4];
#pragma unroll
    for (int mi = 0; mi < 2; mi++)
#pragma unroll
        for (int ni = 0; ni < 4; ni++)
#pragma unroll
            for (int c = 0; c < 4; c++) yacc[mi][ni][c] = 0.f;

    const int nkt = 2 * qt + 2;
    for (int kt = 0; kt < nkt; kt++) {
        __syncthreads();   // Q ready (kt=0) / prev-iter Vs,Ps reads done

        // stage K/V tiles (64x64 each)
        const float* Kt = Kg + (size_t)kt * 64 * 64;
        const float* Vt = Vg + (size_t)kt * 64 * 64;
#pragma unroll
        for (int i = 0; i < 4; i++) {
            int j = i * 256 + tid;
            int r = j >> 4, c4 = (j & 15) * 4;
            float4 kv = *reinterpret_cast<const float4*>(Kt + r * 64 + c4);
            uint32_t* p = &Ks[r * AT_STRIDE + c4];
            p[0] = f2t(kv.x); p[1] = f2t(kv.y); p[2] = f2t(kv.z); p[3] = f2t(kv.w);
            float4 vv = *reinterpret_cast<const float4*>(Vt + r * 64 + c4);
            uint32_t* q = &Vs[r * V_STRIDE + c4];
            q[0] = f2t(vv.x); q[1] = f2t(vv.y); q[2] = f2t(vv.z); q[3] = f2t(vv.w);
        }
        __syncthreads();

        // ---- S = Q @ K^T (128x64, k-depth 64) ----
        float sacc[2][4][4];
#pragma unroll
        for (int mi = 0; mi < 2; mi++)
#pragma unroll
            for (int ni = 0; ni < 4; ni++)
#pragma unroll
                for (int c = 0; c < 4; c++) sacc[mi][ni][c] = 0.f;

#pragma unroll
        for (int kk = 0; kk < 8; kk++) {
            uint2 a[2][2];
#pragma unroll
            for (int mi = 0; mi < 2; mi++) {
                int row = wm * 32 + mi * 16 + g;
                a[mi][0] = *reinterpret_cast<const uint2*>(
                    &Qs[row * AT_STRIDE + kk * 8 + 2 * tg]);
                a[mi][1] = *reinterpret_cast<const uint2*>(
                    &Qs[(row + 8) * AT_STRIDE + kk * 8 + 2 * tg]);
            }
#pragma unroll
            for (int ni = 0; ni < 4; ni++) {
                int col = wn * 32 + ni * 8 + g;     // k-position within tile
                uint2 b = *reinterpret_cast<const uint2*>(
                    &Ks[col * AT_STRIDE + kk * 8 + 2 * tg]);
#pragma unroll
                for (int mi = 0; mi < 2; mi++)
                    mma8(sacc[mi][ni],
                         a[mi][0].x, a[mi][1].x, a[mi][0].y, a[mi][1].y, b.x, b.y);
            }
        }

        // ---- scale, causal mask, relu -> Ps (tf32) ----
        const bool need_mask = (kt >= 2 * qt);
#pragma unroll
        for (int mi = 0; mi < 2; mi++) {
#pragma unroll
            for (int ni = 0; ni < 4; ni++) {
                int rb = wm * 32 + mi * 16;
                int cb = wn * 32 + ni * 8;
#pragma unroll
                for (int half = 0; half < 2; half++) {
                    int qrow = qbase + rb + g + half * 8;
                    int kg0  = kt * 64 + cb + 2 * tg;
                    float v0 = fmaxf(sacc[mi][ni][half * 2 + 0] * SCALE_, 0.f);
                    float v1 = fmaxf(sacc[mi][ni][half * 2 + 1] * SCALE_, 0.f);
                    if (need_mask) {
                        if (kg0 > qrow)     v0 = 0.f;
                        if (kg0 + 1 > qrow) v1 = 0.f;
                    }
                    uint2 pv = make_uint2(f2t(v0), f2t(v1));
                    *reinterpret_cast<uint2*>(
                        &Ps[(rb + g + half * 8) * AT_STRIDE + cb + 2 * tg]) = pv;
                }
            }
        }
        __syncthreads();

        // ---- Y += P @ V (128x64, k-depth 64) ----
#pragma unroll
        for (int kk = 0; kk < 8; kk++) {
            uint2 a[2][2];
#pragma unroll
            for (int mi = 0; mi < 2; mi++) {
                int row = wm * 32 + mi * 16 + g;
                a[mi][0] = *reinterpret_cast<const uint2*>(
                    &Ps[row * AT_STRIDE + kk * 8 + 2 * tg]);
                a[mi][1] = *reinterpret_cast<const uint2*>(
                    &Ps[(row + 8) * AT_STRIDE + kk * 8 + 2 * tg]);
            }
#pragma unroll
            for (int ni = 0; ni < 4; ni++) {
                int col = wn * 32 + ni * 8 + g;     // d column
                uint32_t b0 = Vs[(kk * 8 + 2 * tg) * V_STRIDE + col];
                uint32_t b1 = Vs[(kk * 8 + 2 * tg + 1) * V_STRIDE + col];
#pragma unroll
                for (int mi = 0; mi < 2; mi++)
                    mma8(yacc[mi][ni],
                         a[mi][0].x, a[mi][1].x, a[mi][0].y, a[mi][1].y, b0, b1);
            }
        }
    }

    // ---- write Y to out [B, S, H, D] ----
    const int b = bh / H_, h = bh % H_;
#pragma unroll
    for (int mi = 0; mi < 2; mi++) {
#pragma unroll
        for (int ni = 0; ni < 4; ni++) {
            int d0 = wn * 32 + ni * 8 + 2 * tg;  // even
#pragma unroll
            for (int half = 0; half < 2; half++) {
                int qrow = qbase + wm * 32 + mi * 16 + g + half * 8;
                float2 val = make_float2(yacc[mi][ni][half * 2 + 0],
                                         yacc[mi][ni][half * 2 + 1]);
                *reinterpret_cast<float2*>(
                    &out[(((size_t)b * S_ + qrow) * H_ + h) * D_ + d0]) = val;
            }
        }
    }
}

// ---------------------------------------------------------------------------
extern "C" void kernel_launch(void* const* d_in, const int* in_sizes, int n_in,
                              void* d_out, int out_size)
{
    const float* X    = (const float*)d_in[0];   // [4, 2048, 768]
    const float* W    = (const float*)d_in[1];   // [768, 2304]
    const float* bias = (const float*)d_in[2];   // [2304]
    float* out = (float*)d_out;                  // [4, 2048, 768]

    cudaFuncSetAttribute(attn_kernel,
                         cudaFuncAttributeMaxDynamicSharedMemorySize,
                         ATTN_SMEM_BYTES);

    qkv_gemm<<<dim3(3 * E_ / 128, (B_ * S_) / 128), 256>>>(X, W, bias);
    attn_kernel<<<dim3(S_ / 128, B_ * H_), 256, ATTN_SMEM_BYTES>>>(out);
}

// round 2
// speedup vs baseline: 1.1695x; 1.1695x over previous
#include <cuda_runtime.h>
#include <cstdint>

// Problem constants
#define B_ 4
#define S_ 2048
#define E_ 768
#define H_ 12
#define D_ 64
#define SCALE_ 0.125f   // 1/sqrt(64)

// Scratch for Q/K/V in [B, H, S, D] layout (no cudaMalloc allowed)
__device__ float g_q[(size_t)B_ * H_ * S_ * D_];
__device__ float g_k[(size_t)B_ * H_ * S_ * D_];
__device__ float g_v[(size_t)B_ * H_ * S_ * D_];

// ---------------------------------------------------------------------------
// helpers
// ---------------------------------------------------------------------------
__device__ __forceinline__ uint32_t f2t(float f) {
    uint32_t u;
    asm("cvt.rna.tf32.f32 %0, %1;" : "=r"(u) : "f"(f));
    return u;
}

__device__ __forceinline__ void mma8(float c[4],
                                     uint32_t a0, uint32_t a1, uint32_t a2, uint32_t a3,
                                     uint32_t b0, uint32_t b1) {
    asm volatile(
        "mma.sync.aligned.m16n8k8.row.col.f32.tf32.tf32.f32 "
        "{%0,%1,%2,%3}, {%4,%5,%6,%7}, {%8,%9}, {%0,%1,%2,%3};"
        : "+f"(c[0]), "+f"(c[1]), "+f"(c[2]), "+f"(c[3])
        : "r"(a0), "r"(a1), "r"(a2), "r"(a3), "r"(b0), "r"(b1));
}

// ---------------------------------------------------------------------------
// Kernel 1: fused QKV projection  C[8192, 2304] = X[8192,768] @ W[768,2304] + b
// Scatters result into g_q / g_k / g_v as [B,H,S,D].
// Block: 256 threads (8 warps, 4x2), tile 128x128, BK=32, TF32 mma.
// ---------------------------------------------------------------------------
#define GA_STRIDE 40    // As[m][k] padded stride
#define GB_STRIDE 140   // Bs[k][n] padded stride

__global__ __launch_bounds__(256, 2) void qkv_gemm(
    const float* __restrict__ X, const float* __restrict__ W,
    const float* __restrict__ bias)
{
    __shared__ uint32_t As[128 * GA_STRIDE];   // 128 x 32 (tf32)
    __shared__ uint32_t Bs[32 * GB_STRIDE];    // 32 x 128 (tf32)

    const int tid  = threadIdx.x;
    const int lane = tid & 31;
    const int wid  = tid >> 5;
    const int g    = lane >> 2;     // groupID 0..7
    const int tg   = lane & 3;      // thread-in-group 0..3
    const int wm   = wid & 3;       // warp row 0..3 (32 rows each)
    const int wn   = wid >> 2;      // warp col 0..1 (64 cols each)
    const int mbase = blockIdx.y * 128;
    const int nbase = blockIdx.x * 128;

    float acc[2][8][4];
#pragma unroll
    for (int mi = 0; mi < 2; mi++)
#pragma unroll
        for (int ni = 0; ni < 8; ni++)
#pragma unroll
            for (int c = 0; c < 4; c++) acc[mi][ni][c] = 0.f;

    for (int k0 = 0; k0 < E_; k0 += 32) {
        // A tile 128x32 (row-major)
#pragma unroll
        for (int i = 0; i < 4; i++) {
            int j = i * 256 + tid;
            int r = j >> 3, c4 = (j & 7) * 4;
            float4 v = *reinterpret_cast<const float4*>(
                X + (size_t)(mbase + r) * E_ + k0 + c4);
            uint4 t = make_uint4(f2t(v.x), f2t(v.y), f2t(v.z), f2t(v.w));
            *reinterpret_cast<uint4*>(&As[r * GA_STRIDE + c4]) = t;
        }
        // B tile 32x128 (natural [k][n])
#pragma unroll
        for (int i = 0; i < 4; i++) {
            int j = i * 256 + tid;
            int kr = j >> 5, c4 = (j & 31) * 4;
            float4 v = *reinterpret_cast<const float4*>(
                W + (size_t)(k0 + kr) * (3 * E_) + nbase + c4);
            uint4 t = make_uint4(f2t(v.x), f2t(v.y), f2t(v.z), f2t(v.w));
            *reinterpret_cast<uint4*>(&Bs[kr * GB_STRIDE + c4]) = t;
        }
        __syncthreads();

#pragma unroll
        for (int kk = 0; kk < 4; kk++) {
            // permuted k-slots: thread tg owns logical k = kk*8 + {2tg, 2tg+1}
            uint2 a[2][2];
#pragma unroll
            for (int mi = 0; mi < 2; mi++) {
                int row = wm * 32 + mi * 16 + g;
                a[mi][0] = *reinterpret_cast<const uint2*>(
                    &As[row * GA_STRIDE + kk * 8 + 2 * tg]);
                a[mi][1] = *reinterpret_cast<const uint2*>(
                    &As[(row + 8) * GA_STRIDE + kk * 8 + 2 * tg]);
            }
#pragma unroll
            for (int ni = 0; ni < 8; ni++) {
                int col = wn * 64 + ni * 8 + g;
                uint32_t b0 = Bs[(kk * 8 + 2 * tg) * GB_STRIDE + col];
                uint32_t b1 = Bs[(kk * 8 + 2 * tg + 1) * GB_STRIDE + col];
#pragma unroll
                for (int mi = 0; mi < 2; mi++)
                    mma8(acc[mi][ni],
                         a[mi][0].x, a[mi][1].x, a[mi][0].y, a[mi][1].y, b0, b1);
            }
        }
        __syncthreads();
    }

    // Epilogue: + bias, scatter into g_q/g_k/g_v as [B,H,S,D]
#pragma unroll
    for (int mi = 0; mi < 2; mi++) {
#pragma unroll
        for (int ni = 0; ni < 8; ni++) {
            int n = nbase + wn * 64 + ni * 8 + 2 * tg;   // even
            int which = n / E_;
            int n2 = n - which * E_;
            int h = n2 >> 6, d = n2 & 63;
            float b0 = __ldg(bias + n), b1 = __ldg(bias + n + 1);
            float* basep = (which == 0) ? g_q : ((which == 1) ? g_k : g_v);
#pragma unroll
            for (int half = 0; half < 2; half++) {
                int m = mbase + wm * 32 + mi * 16 + g + half * 8;
                int b = m >> 11;          // m / 2048
                int s = m & 2047;
                float2 val = make_float2(acc[mi][ni][half * 2 + 0] + b0,
                                         acc[mi][ni][half * 2 + 1] + b1);
                *reinterpret_cast<float2*>(
                    basep + ((((size_t)b * H_ + h) * S_ + s) * D_ + d)) = val;
            }
        }
    }
}

// ---------------------------------------------------------------------------
// Kernel 2: causal ReLU attention per (q-tile 128, head).
//   8 warps x 16 q-rows each. S-accumulator is reused IN REGISTERS as the
//   A-operand of the Y GEMM (C fragment == A fragment under the permuted-k
//   layout) -> no P SMEM round trip, no inter-phase barrier.
// Only kt <= 2*qt+1 tiles are visited (causal skipping).
// ---------------------------------------------------------------------------
#define AT_STRIDE 72   // Qs/Ks stride (conflict-free LDS.64 frag loads)
#define V_STRIDE  68   // Vs stride (conflict-free LDS.32 frag loads)
#define ATTN_SMEM_WORDS (128 * AT_STRIDE + 64 * AT_STRIDE + 64 * V_STRIDE)
#define ATTN_SMEM_BYTES (ATTN_SMEM_WORDS * 4)

__global__ __launch_bounds__(256, 2) void attn_kernel(float* __restrict__ out)
{
    extern __shared__ uint32_t sh[];
    uint32_t* Qs = sh;                          // [128][72]  Q tile (tf32)
    uint32_t* Ks = Qs + 128 * AT_STRIDE;        // [64][72]   K tile
    uint32_t* Vs = Ks + 64 * AT_STRIDE;         // [64][68]   V tile (natural [s][d])

    const int tid  = threadIdx.x;
    const int lane = tid & 31;
    const int w    = tid >> 5;   // warp 0..7, rows [w*16, w*16+16)
    const int g    = lane >> 2;
    const int tg   = lane & 3;
    const int qt   = blockIdx.x;
    const int bh   = blockIdx.y;
    const int qbase = qt * 128;

    const float* Qg = g_q + (size_t)bh * S_ * D_ + (size_t)qbase * D_;
    const float* Kg = g_k + (size_t)bh * S_ * D_;
    const float* Vg = g_v + (size_t)bh * S_ * D_;

    // stage Q tile (128x64) as tf32
#pragma unroll
    for (int i = 0; i < 8; i++) {
        int j = i * 256 + tid;
        int r = j >> 4, c4 = (j & 15) * 4;
        float4 v = *reinterpret_cast<const float4*>(Qg + r * 64 + c4);
        uint4 t = make_uint4(f2t(v.x), f2t(v.y), f2t(v.z), f2t(v.w));
        *reinterpret_cast<uint4*>(&Qs[r * AT_STRIDE + c4]) = t;
    }

    float yacc[8][4];
#pragma unroll
    for (int ni = 0; ni < 8; ni++)
#pragma unroll
        for (int c = 0; c < 4; c++) yacc[ni][c] = 0.f;

    const int r0 = qbase + w * 16 + g;   // this thread's even q-row
    const int qrow0 = w * 16 + g;        // within-tile row

    const int nkt = 2 * qt + 2;
    for (int kt = 0; kt < nkt; kt++) {
        __syncthreads();   // Q ready (kt=0) / prev-iter Ks,Vs reads done

        // stage K/V tiles (64x64 each)
        const float* Kt = Kg + (size_t)kt * 64 * 64;
        const float* Vt = Vg + (size_t)kt * 64 * 64;
#pragma unroll
        for (int i = 0; i < 4; i++) {
            int j = i * 256 + tid;
            int r = j >> 4, c4 = (j & 15) * 4;
            float4 kv = *reinterpret_cast<const float4*>(Kt + r * 64 + c4);
            uint4 tk = make_uint4(f2t(kv.x), f2t(kv.y), f2t(kv.z), f2t(kv.w));
            *reinterpret_cast<uint4*>(&Ks[r * AT_STRIDE + c4]) = tk;
            float4 vv = *reinterpret_cast<const float4*>(Vt + r * 64 + c4);
            uint4 tv = make_uint4(f2t(vv.x), f2t(vv.y), f2t(vv.z), f2t(vv.w));
            *reinterpret_cast<uint4*>(&Vs[r * V_STRIDE + c4]) = tv;
        }
        __syncthreads();

        // ---- S = Q @ K^T : 16 rows x 64 cols, k-depth 64 ----
        float sacc[8][4];
#pragma unroll
        for (int ni = 0; ni < 8; ni++)
#pragma unroll
            for (int c = 0; c < 4; c++) sacc[ni][c] = 0.f;

#pragma unroll
        for (int kk = 0; kk < 8; kk++) {
            uint2 a0 = *reinterpret_cast<const uint2*>(
                &Qs[qrow0 * AT_STRIDE + kk * 8 + 2 * tg]);
            uint2 a1 = *reinterpret_cast<const uint2*>(
                &Qs[(qrow0 + 8) * AT_STRIDE + kk * 8 + 2 * tg]);
#pragma unroll
            for (int ni = 0; ni < 8; ni++) {
                uint2 b = *reinterpret_cast<const uint2*>(
                    &Ks[(ni * 8 + g) * AT_STRIDE + kk * 8 + 2 * tg]);
                mma8(sacc[ni], a0.x, a1.x, a0.y, a1.y, b.x, b.y);
            }
        }

        // ---- scale, causal mask, relu, cvt->tf32 IN PLACE ----
        const bool need_mask = (kt >= 2 * qt);
#pragma unroll
        for (int ni = 0; ni < 8; ni++) {
            int c0 = kt * 64 + ni * 8 + 2 * tg;
            float v0 = fmaxf(sacc[ni][0] * SCALE_, 0.f);
            float v1 = fmaxf(sacc[ni][1] * SCALE_, 0.f);
            float v2 = fmaxf(sacc[ni][2] * SCALE_, 0.f);
            float v3 = fmaxf(sacc[ni][3] * SCALE_, 0.f);
            if (need_mask) {
                if (c0 > r0)         v0 = 0.f;
                if (c0 + 1 > r0)     v1 = 0.f;
                if (c0 > r0 + 8)     v2 = 0.f;
                if (c0 + 1 > r0 + 8) v3 = 0.f;
            }
            sacc[ni][0] = __uint_as_float(f2t(v0));
            sacc[ni][1] = __uint_as_float(f2t(v1));
            sacc[ni][2] = __uint_as_float(f2t(v2));
            sacc[ni][3] = __uint_as_float(f2t(v3));
        }

        // ---- Y += P @ V : P is the sacc registers (C frag == A frag) ----
#pragma unroll
        for (int kk = 0; kk < 8; kk++) {
            uint32_t a0 = __float_as_uint(sacc[kk][0]);  // (g,   2tg)
            uint32_t a1 = __float_as_uint(sacc[kk][2]);  // (g+8, 2tg)
            uint32_t a2 = __float_as_uint(sacc[kk][1]);  // (g,   2tg+1)
            uint32_t a3 = __float_as_uint(sacc[kk][3]);  // (g+8, 2tg+1)
#pragma unroll
            for (int ni = 0; ni < 8; ni++) {
                uint32_t b0 = Vs[(kk * 8 + 2 * tg) * V_STRIDE + ni * 8 + g];
                uint32_t b1 = Vs[(kk * 8 + 2 * tg + 1) * V_STRIDE + ni * 8 + g];
                mma8(yacc[ni], a0, a1, a2, a3, b0, b1);
            }
        }
    }

    // ---- write Y to out [B, S, H, D] ----
    const int b = bh / H_, h = bh % H_;
#pragma unroll
    for (int ni = 0; ni < 8; ni++) {
        int d0 = ni * 8 + 2 * tg;  // even
        float2 v0 = make_float2(yacc[ni][0], yacc[ni][1]);
        *reinterpret_cast<float2*>(
            &out[(((size_t)b * S_ + r0) * H_ + h) * D_ + d0]) = v0;
        float2 v1 = make_float2(yacc[ni][2], yacc[ni][3]);
        *reinterpret_cast<float2*>(
            &out[(((size_t)b * S_ + r0 + 8) * H_ + h) * D_ + d0]) = v1;
    }
}

// ---------------------------------------------------------------------------
extern "C" void kernel_launch(void* const* d_in, const int* in_sizes, int n_in,
                              void* d_out, int out_size)
{
    const float* X    = (const float*)d_in[0];   // [4, 2048, 768]
    const float* W    = (const float*)d_in[1];   // [768, 2304]
    const float* bias = (const float*)d_in[2];   // [2304]
    float* out = (float*)d_out;                  // [4, 2048, 768]

    cudaFuncSetAttribute(attn_kernel,
                         cudaFuncAttributeMaxDynamicSharedMemorySize,
                         ATTN_SMEM_BYTES);

    qkv_gemm<<<dim3(3 * E_ / 128, (B_ * S_) / 128), 256>>>(X, W, bias);
    attn_kernel<<<dim3(S_ / 128, B_ * H_), 256, ATTN_SMEM_BYTES>>>(out);
}

// round 3
// speedup vs baseline: 1.2950x; 1.1074x over previous
#include <cuda_runtime.h>
#include <cstdint>

// Problem constants
#define B_ 4
#define S_ 2048
#define E_ 768
#define H_ 12
#define D_ 64
#define SCALE_ 0.125f   // 1/sqrt(64)

// Scratch (no cudaMalloc allowed)
__device__ float g_q[(size_t)B_ * H_ * S_ * D_];
__device__ float g_k[(size_t)B_ * H_ * S_ * D_];
__device__ float g_v[(size_t)B_ * H_ * S_ * D_];
__device__ float g_x[(size_t)B_ * S_ * E_];      // tf32-rounded X
__device__ float g_w[(size_t)E_ * 3 * E_];       // tf32-rounded W

// ---------------------------------------------------------------------------
// helpers
// ---------------------------------------------------------------------------
__device__ __forceinline__ uint32_t f2t(float f) {
    uint32_t u;
    asm("cvt.rna.tf32.f32 %0, %1;" : "=r"(u) : "f"(f));
    return u;
}

__device__ __forceinline__ void mma8(float c[4],
                                     uint32_t a0, uint32_t a1, uint32_t a2, uint32_t a3,
                                     uint32_t b0, uint32_t b1) {
    asm volatile(
        "mma.sync.aligned.m16n8k8.row.col.f32.tf32.tf32.f32 "
        "{%0,%1,%2,%3}, {%4,%5,%6,%7}, {%8,%9}, {%0,%1,%2,%3};"
        : "+f"(c[0]), "+f"(c[1]), "+f"(c[2]), "+f"(c[3])
        : "r"(a0), "r"(a1), "r"(a2), "r"(a3), "r"(b0), "r"(b1));
}

__device__ __forceinline__ void cp16(void* sdst, const void* gsrc) {
    uint32_t a = (uint32_t)__cvta_generic_to_shared(sdst);
    asm volatile("cp.async.cg.shared.global [%0], [%1], 16;"
                 :: "r"(a), "l"(gsrc));
}
#define CP_COMMIT() asm volatile("cp.async.commit_group;")
#define CP_WAIT0()  asm volatile("cp.async.wait_group 0;")

// ---------------------------------------------------------------------------
// Kernel 0: elementwise rna tf32 rounding (float4 vectorized)
// ---------------------------------------------------------------------------
__global__ void cvt_kernel(const float4* __restrict__ src,
                           uint4* __restrict__ dst, int n4)
{
    int i = blockIdx.x * blockDim.x + threadIdx.x;
    if (i < n4) {
        float4 v = src[i];
        dst[i] = make_uint4(f2t(v.x), f2t(v.y), f2t(v.z), f2t(v.w));
    }
}

// ---------------------------------------------------------------------------
// Kernel 1: fused QKV projection  C[8192, 2304] = Xt @ Wt + b   (tf32 mma)
// Inputs g_x/g_w are pre-rounded tf32. cp.async staging, double-buffered,
// BK=32. Epilogue stores Q/K/V rna-rounded into [B,H,S,D] scratch.
// ---------------------------------------------------------------------------
#define GA_STRIDE 40    // As[m][k] padded stride (words)
#define GB_STRIDE 140   // Bs[k][n] padded stride (words)
#define GEMM_SMEM_WORDS (2 * 128 * GA_STRIDE + 2 * 32 * GB_STRIDE)
#define GEMM_SMEM_BYTES (GEMM_SMEM_WORDS * 4)

__global__ __launch_bounds__(256, 2) void qkv_gemm(const float* __restrict__ bias)
{
    extern __shared__ uint32_t shg[];
    uint32_t* As = shg;                         // [2][128][40]
    uint32_t* Bs = shg + 2 * 128 * GA_STRIDE;   // [2][32][140]

    const int tid  = threadIdx.x;
    const int lane = tid & 31;
    const int wid  = tid >> 5;
    const int g    = lane >> 2;
    const int tg   = lane & 3;
    const int wm   = wid & 3;
    const int wn   = wid >> 2;
    const int mbase = blockIdx.y * 128;
    const int nbase = blockIdx.x * 128;

    const float* X = g_x;
    const float* W = g_w;

    float acc[2][8][4];
#pragma unroll
    for (int mi = 0; mi < 2; mi++)
#pragma unroll
        for (int ni = 0; ni < 8; ni++)
#pragma unroll
            for (int c = 0; c < 4; c++) acc[mi][ni][c] = 0.f;

    // tile stagers (cp.async, 16B chunks)
    auto stage = [&](int buf, int k0) {
        uint32_t* Ab = As + buf * 128 * GA_STRIDE;
        uint32_t* Bb = Bs + buf * 32 * GB_STRIDE;
#pragma unroll
        for (int i = 0; i < 4; i++) {            // A: 128x32
            int j = i * 256 + tid;
            int r = j >> 3, c4 = (j & 7) * 4;
            cp16(&Ab[r * GA_STRIDE + c4],
                 X + (size_t)(mbase + r) * E_ + k0 + c4);
        }
#pragma unroll
        for (int i = 0; i < 4; i++) {            // B: 32x128
            int j = i * 256 + tid;
            int kr = j >> 5, c4 = (j & 31) * 4;
            cp16(&Bb[kr * GB_STRIDE + c4],
                 W + (size_t)(k0 + kr) * (3 * E_) + nbase + c4);
        }
    };

    const int NK = E_ / 32;   // 24
    stage(0, 0);
    CP_COMMIT();

    for (int ks = 0; ks < NK; ks++) {
        CP_WAIT0();
        __syncthreads();
        if (ks + 1 < NK) {
            stage((ks + 1) & 1, (ks + 1) * 32);
            CP_COMMIT();
        }
        uint32_t* Ab = As + (ks & 1) * 128 * GA_STRIDE;
        uint32_t* Bb = Bs + (ks & 1) * 32 * GB_STRIDE;

#pragma unroll
        for (int kk = 0; kk < 4; kk++) {
            uint2 a[2][2];
#pragma unroll
            for (int mi = 0; mi < 2; mi++) {
                int row = wm * 32 + mi * 16 + g;
                a[mi][0] = *reinterpret_cast<const uint2*>(
                    &Ab[row * GA_STRIDE + kk * 8 + 2 * tg]);
                a[mi][1] = *reinterpret_cast<const uint2*>(
                    &Ab[(row + 8) * GA_STRIDE + kk * 8 + 2 * tg]);
            }
#pragma unroll
            for (int ni = 0; ni < 8; ni++) {
                int col = wn * 64 + ni * 8 + g;
                uint32_t b0 = Bb[(kk * 8 + 2 * tg) * GB_STRIDE + col];
                uint32_t b1 = Bb[(kk * 8 + 2 * tg + 1) * GB_STRIDE + col];
#pragma unroll
                for (int mi = 0; mi < 2; mi++)
                    mma8(acc[mi][ni],
                         a[mi][0].x, a[mi][1].x, a[mi][0].y, a[mi][1].y, b0, b1);
            }
        }
    }

    // Epilogue: + bias, rna-round, scatter into g_q/g_k/g_v as [B,H,S,D]
#pragma unroll
    for (int mi = 0; mi < 2; mi++) {
#pragma unroll
        for (int ni = 0; ni < 8; ni++) {
            int n = nbase + wn * 64 + ni * 8 + 2 * tg;   // even
            int which = n / E_;
            int n2 = n - which * E_;
            int h = n2 >> 6, d = n2 & 63;
            float b0 = __ldg(bias + n), b1 = __ldg(bias + n + 1);
            float* basep = (which == 0) ? g_q : ((which == 1) ? g_k : g_v);
#pragma unroll
            for (int half = 0; half < 2; half++) {
                int m = mbase + wm * 32 + mi * 16 + g + half * 8;
                int b = m >> 11;
                int s = m & 2047;
                float2 val = make_float2(
                    __uint_as_float(f2t(acc[mi][ni][half * 2 + 0] + b0)),
                    __uint_as_float(f2t(acc[mi][ni][half * 2 + 1] + b1)));
                *reinterpret_cast<float2*>(
                    basep + ((((size_t)b * H_ + h) * S_ + s) * D_ + d)) = val;
            }
        }
    }
}

// ---------------------------------------------------------------------------
// Kernel 2: causal ReLU attention, 8 warps x 16 q-rows, register S->P->Y
// dataflow, cp.async staging with double-buffered K/V tiles.
// ---------------------------------------------------------------------------
#define AT_STRIDE 72
#define V_STRIDE  68
#define ATTN_SMEM_WORDS (128 * AT_STRIDE + 2 * 64 * AT_STRIDE + 2 * 64 * V_STRIDE)
#define ATTN_SMEM_BYTES (ATTN_SMEM_WORDS * 4)

__global__ __launch_bounds__(256, 2) void attn_kernel(float* __restrict__ out)
{
    extern __shared__ uint32_t sh[];
    uint32_t* Qs = sh;                               // [128][72]
    uint32_t* Ks = Qs + 128 * AT_STRIDE;             // [2][64][72]
    uint32_t* Vs = Ks + 2 * 64 * AT_STRIDE;          // [2][64][68]

    const int tid  = threadIdx.x;
    const int lane = tid & 31;
    const int w    = tid >> 5;
    const int g    = lane >> 2;
    const int tg   = lane & 3;
    const int qt   = blockIdx.x;
    const int bh   = blockIdx.y;
    const int qbase = qt * 128;

    const float* Qg = g_q + (size_t)bh * S_ * D_ + (size_t)qbase * D_;
    const float* Kg = g_k + (size_t)bh * S_ * D_;
    const float* Vg = g_v + (size_t)bh * S_ * D_;

    auto stageKV = [&](int buf, int kt) {
        uint32_t* Kb = Ks + buf * 64 * AT_STRIDE;
        uint32_t* Vb = Vs + buf * 64 * V_STRIDE;
        const float* Kt = Kg + (size_t)kt * 64 * 64;
        const float* Vt = Vg + (size_t)kt * 64 * 64;
#pragma unroll
        for (int i = 0; i < 4; i++) {
            int j = i * 256 + tid;
            int r = j >> 4, c4 = (j & 15) * 4;
            cp16(&Kb[r * AT_STRIDE + c4], Kt + r * 64 + c4);
            cp16(&Vb[r * V_STRIDE + c4], Vt + r * 64 + c4);
        }
    };

    // prologue: stage Q + first K/V tile
#pragma unroll
    for (int i = 0; i < 8; i++) {
        int j = i * 256 + tid;
        int r = j >> 4, c4 = (j & 15) * 4;
        cp16(&Qs[r * AT_STRIDE + c4], Qg + r * 64 + c4);
    }
    stageKV(0, 0);
    CP_COMMIT();

    float yacc[8][4];
#pragma unroll
    for (int ni = 0; ni < 8; ni++)
#pragma unroll
        for (int c = 0; c < 4; c++) yacc[ni][c] = 0.f;

    const int r0 = qbase + w * 16 + g;
    const int qrow0 = w * 16 + g;

    const int nkt = 2 * qt + 2;
    for (int kt = 0; kt < nkt; kt++) {
        CP_WAIT0();
        __syncthreads();
        if (kt + 1 < nkt) {
            stageKV((kt + 1) & 1, kt + 1);
            CP_COMMIT();
        }
        uint32_t* Kb = Ks + (kt & 1) * 64 * AT_STRIDE;
        uint32_t* Vb = Vs + (kt & 1) * 64 * V_STRIDE;

        // ---- S = Q @ K^T : 16 rows x 64 cols, k-depth 64 ----
        float sacc[8][4];
#pragma unroll
        for (int ni = 0; ni < 8; ni++)
#pragma unroll
            for (int c = 0; c < 4; c++) sacc[ni][c] = 0.f;

#pragma unroll
        for (int kk = 0; kk < 8; kk++) {
            uint2 a0 = *reinterpret_cast<const uint2*>(
                &Qs[qrow0 * AT_STRIDE + kk * 8 + 2 * tg]);
            uint2 a1 = *reinterpret_cast<const uint2*>(
                &Qs[(qrow0 + 8) * AT_STRIDE + kk * 8 + 2 * tg]);
#pragma unroll
            for (int ni = 0; ni < 8; ni++) {
                uint2 b = *reinterpret_cast<const uint2*>(
                    &Kb[(ni * 8 + g) * AT_STRIDE + kk * 8 + 2 * tg]);
                mma8(sacc[ni], a0.x, a1.x, a0.y, a1.y, b.x, b.y);
            }
        }

        // ---- scale, causal mask, relu, cvt->tf32 IN PLACE ----
        const bool need_mask = (kt >= 2 * qt);
#pragma unroll
        for (int ni = 0; ni < 8; ni++) {
            int c0 = kt * 64 + ni * 8 + 2 * tg;
            float v0 = fmaxf(sacc[ni][0] * SCALE_, 0.f);
            float v1 = fmaxf(sacc[ni][1] * SCALE_, 0.f);
            float v2 = fmaxf(sacc[ni][2] * SCALE_, 0.f);
            float v3 = fmaxf(sacc[ni][3] * SCALE_, 0.f);
            if (need_mask) {
                if (c0 > r0)         v0 = 0.f;
                if (c0 + 1 > r0)     v1 = 0.f;
                if (c0 > r0 + 8)     v2 = 0.f;
                if (c0 + 1 > r0 + 8) v3 = 0.f;
            }
            sacc[ni][0] = __uint_as_float(f2t(v0));
            sacc[ni][1] = __uint_as_float(f2t(v1));
            sacc[ni][2] = __uint_as_float(f2t(v2));
            sacc[ni][3] = __uint_as_float(f2t(v3));
        }

        // ---- Y += P @ V : P lives in sacc registers (C frag == A frag) ----
#pragma unroll
        for (int kk = 0; kk < 8; kk++) {
            uint32_t a0 = __float_as_uint(sacc[kk][0]);
            uint32_t a1 = __float_as_uint(sacc[kk][2]);
            uint32_t a2 = __float_as_uint(sacc[kk][1]);
            uint32_t a3 = __float_as_uint(sacc[kk][3]);
#pragma unroll
            for (int ni = 0; ni < 8; ni++) {
                uint32_t b0 = Vb[(kk * 8 + 2 * tg) * V_STRIDE + ni * 8 + g];
                uint32_t b1 = Vb[(kk * 8 + 2 * tg + 1) * V_STRIDE + ni * 8 + g];
                mma8(yacc[ni], a0, a1, a2, a3, b0, b1);
            }
        }
    }

    // ---- write Y to out [B, S, H, D] ----
    const int b = bh / H_, h = bh % H_;
#pragma unroll
    for (int ni = 0; ni < 8; ni++) {
        int d0 = ni * 8 + 2 * tg;
        float2 v0 = make_float2(yacc[ni][0], yacc[ni][1]);
        *reinterpret_cast<float2*>(
            &out[(((size_t)b * S_ + r0) * H_ + h) * D_ + d0]) = v0;
        float2 v1 = make_float2(yacc[ni][2], yacc[ni][3]);
        *reinterpret_cast<float2*>(
            &out[(((size_t)b * S_ + r0 + 8) * H_ + h) * D_ + d0]) = v1;
    }
}

// ---------------------------------------------------------------------------
extern "C" void kernel_launch(void* const* d_in, const int* in_sizes, int n_in,
                              void* d_out, int out_size)
{
    const float* X    = (const float*)d_in[0];   // [4, 2048, 768]
    const float* W    = (const float*)d_in[1];   // [768, 2304]
    const float* bias = (const float*)d_in[2];   // [2304]
    float* out = (float*)d_out;                  // [4, 2048, 768]

    static bool attr_done = false;
    if (!attr_done) {
        cudaFuncSetAttribute(qkv_gemm,
                             cudaFuncAttributeMaxDynamicSharedMemorySize,
                             GEMM_SMEM_BYTES);
        cudaFuncSetAttribute(attn_kernel,
                             cudaFuncAttributeMaxDynamicSharedMemorySize,
                             ATTN_SMEM_BYTES);
        attr_done = true;
    }

    // round inputs to tf32 once per launch (deterministic, idempotent)
    {
        float* gx;  cudaGetSymbolAddress((void**)&gx, g_x);
        float* gw;  cudaGetSymbolAddress((void**)&gw, g_w);
        int nx4 = (B_ * S_ * E_) / 4;
        int nw4 = (E_ * 3 * E_) / 4;
        cvt_kernel<<<(nx4 + 255) / 256, 256>>>(
            (const float4*)X, (uint4*)gx, nx4);
        cvt_kernel<<<(nw4 + 255) / 256, 256>>>(
            (const float4*)W, (uint4*)gw, nw4);
    }

    qkv_gemm<<<dim3(3 * E_ / 128, (B_ * S_) / 128), 256, GEMM_SMEM_BYTES>>>(bias);
    attn_kernel<<<dim3(S_ / 128, B_ * H_), 256, ATTN_SMEM_BYTES>>>(out);
}